// round 16
// baseline (speedup 1.0000x reference)
#include <cuda_runtime.h>
#include <cuda_bf16.h>
#include <mma.h>
#include <cstdint>

using namespace nvcuda;

#define DI __device__ __forceinline__

static constexpr int NT  = 512;   // 16 warps, ONE 2-batch CTA per SM
static constexpr int SB  = 136;   // bf16 tile stride (elems)
static constexpr int SP  = 72;    // P (alphas) bf16 stride
static constexpr int SFP = 132;   // fp32 in-place convert stride
static constexpr int SSC = 68;    // fp32 scores stride (64 valid cols per row)
static constexpr int SW  = 40;    // W quarter-buffer stride (32 k + 8 pad)

// ---- smem byte offsets; tiles are [128][SB] bf16 = 34816 B ----
static constexpr int XHI = 0;
static constexpr int XLO = 34816;
static constexpr int THI = 69632;    // T hi; then scores fp32 [128][SSC]; then P hi
static constexpr int TLO = 104448;   // T lo (dead after scores)
static constexpr int PHI = 69632;    // P hi [128][SP] = 18432
static constexpr int PLO = 88064;    // P lo            (ends 106496)
static constexpr int VHI = 139264;   // V hi
static constexpr int VLO = 174080;   // V lo (ends 208896)
static constexpr int QB0 = 208896;   // W quarter buffers [128][SW] bf16 = 10240 each
static constexpr int QB1 = 219136;
static constexpr int SMEM_BYTES = 229376;   // 1 CTA/SM

// prepped: slot0 = G^T (G = Wq·Wk^T), slot1 = Wv^T, slot2 = Wr^T (bf16 hi/lo)
__device__ __align__(16) __nv_bfloat16 g_Whi[3][128 * 128];
__device__ __align__(16) __nv_bfloat16 g_Wlo[3][128 * 128];

DI unsigned pack2(__nv_bfloat16 a, __nv_bfloat16 b) {
    return (unsigned)__bfloat16_as_ushort(a) | ((unsigned)__bfloat16_as_ushort(b) << 16);
}
DI void split2(float v0, float v1, unsigned& h, unsigned& l) {
    __nv_bfloat16 h0 = __float2bfloat16_rn(v0), h1 = __float2bfloat16_rn(v1);
    __nv_bfloat16 l0 = __float2bfloat16_rn(v0 - __bfloat162float(h0));
    __nv_bfloat16 l1 = __float2bfloat16_rn(v1 - __bfloat162float(h1));
    h = pack2(h0, h1); l = pack2(l0, l1);
}
DI void cpa16(uint32_t dst, const void* src) {
    asm volatile("cp.async.cg.shared.global [%0], [%1], 16;" :: "r"(dst), "l"(src));
}
#define CPA_COMMIT() asm volatile("cp.async.commit_group;" ::: "memory")
#define CPA_WAIT0()  asm volatile("cp.async.wait_group 0;" ::: "memory")

// ------------------------------------------------ merged prep kernel
__global__ void prep_all(const float* __restrict__ Wq, const float* __restrict__ Wk,
                         const float* __restrict__ Wv, const float* __restrict__ Wr) {
    const int blk = blockIdx.x;
    if (blk < 128) {
        int gid = blk * 256 + threadIdx.x;
        int o = gid >> 1, half = gid & 1;
        int j = o >> 7, d = o & 127;
        const float4* wq = (const float4*)(Wq + d * 128) + half * 16;
        const float4* wk = (const float4*)(Wk + j * 128) + half * 16;
        float s = 0.f;
#pragma unroll
        for (int e = 0; e < 16; e++) {
            float4 a = wq[e], c = wk[e];
            s = fmaf(a.x, c.x, fmaf(a.y, c.y, fmaf(a.z, c.z, fmaf(a.w, c.w, s))));
        }
        s += __shfl_xor_sync(0xffffffffu, s, 1);
        if (!half) {
            __nv_bfloat16 hi = __float2bfloat16_rn(s);
            g_Whi[0][j * 128 + d] = hi;
            g_Wlo[0][j * 128 + d] = __float2bfloat16_rn(s - __bfloat162float(hi));
        }
    } else {
        int i = (blk - 128) * 256 + threadIdx.x;
        int p = i >> 14, rem = i & 16383;
        int d = rem >> 7, e = rem & 127;
        float w = (p ? Wr : Wv)[rem];
        __nv_bfloat16 hi = __float2bfloat16_rn(w);
        g_Whi[p + 1][e * 128 + d] = hi;
        g_Wlo[p + 1][e * 128 + d] = __float2bfloat16_rn(w - __bfloat162float(hi));
    }
}

// ---------------------------------------------------------------- main kernel
using FA  = wmma::fragment<wmma::matrix_a, 16, 16, 16, __nv_bfloat16, wmma::row_major>;
using FBc = wmma::fragment<wmma::matrix_b, 16, 16, 16, __nv_bfloat16, wmma::col_major>;
using FBr = wmma::fragment<wmma::matrix_b, 16, 16, 16, __nv_bfloat16, wmma::row_major>;
using FC  = wmma::fragment<wmma::accumulator, 16, 16, 16, float>;

__global__ __launch_bounds__(NT, 1)
void autoint_hmma(const float* __restrict__ x, float* __restrict__ out) {
    extern __shared__ __align__(16) char sm[];
    const uint32_t smb = (uint32_t)__cvta_generic_to_shared(sm);
    const int tid = threadIdx.x;
    const int wid = tid >> 5;
    const size_t xbase = (size_t)blockIdx.x * 16384;   // 2 batches, 128 rows

    // 2x2 warp tiles over [128 x 128]: 16 warps x 4 tiles
    const int m0 = 32 * (wid >> 2);     // {0,32,64,96}
    const int n0 = 32 * (wid & 3);      // {0,32,64,96}
    const int g  = wid >> 3;            // batch of this warp's m-range (m0>=64 -> 1)

    const __nv_bfloat16* xhi = (const __nv_bfloat16*)(sm + XHI);
    const __nv_bfloat16* xlo = (const __nv_bfloat16*)(sm + XLO);

    // stage k-quarter q of prepped matrix `slot` into quarter buffer `buf`
    auto stageQ = [&](int slot, int q, int hi, int buf) {
        const char* gsrc = (const char*)(hi ? g_Whi[slot] : g_Wlo[slot]);
        const uint32_t base = smb + (buf ? QB1 : QB0);
        int row = tid >> 2, cc = tid & 3;            // 512 chunks of 16B
        cpa16(base + row * (SW * 2) + cc * 16, gsrc + (row * 128 + q * 32 + cc * 8) * 2);
        CPA_COMMIT();
    };

    // 3-term projection GEMM: acc += X @ W[slot]; K staged in quarters (hi in QB0, lo in QB1)
    auto proj = [&](int slot, FC (&acc)[2][2]) {
#pragma unroll 1
        for (int q = 0; q < 4; q++) {
            stageQ(slot, q, 1, 0);
            stageQ(slot, q, 0, 1);
            CPA_WAIT0();
            __syncthreads();
            const __nv_bfloat16* wqh = (const __nv_bfloat16*)(sm + QB0);
            const __nv_bfloat16* wql = (const __nv_bfloat16*)(sm + QB1);
#pragma unroll
            for (int kk = 0; kk < 32; kk += 16) {
                const int k = q * 32 + kk;
                FA ah[2], al[2];
                FBc bh[2], bl[2];
#pragma unroll
                for (int i = 0; i < 2; i++) {
                    wmma::load_matrix_sync(ah[i], xhi + (m0 + 16 * i) * SB + k, SB);
                    wmma::load_matrix_sync(al[i], xlo + (m0 + 16 * i) * SB + k, SB);
                }
#pragma unroll
                for (int j = 0; j < 2; j++) {
                    wmma::load_matrix_sync(bh[j], wqh + (n0 + 16 * j) * SW + kk, SW);
                    wmma::load_matrix_sync(bl[j], wql + (n0 + 16 * j) * SW + kk, SW);
                }
#pragma unroll
                for (int i = 0; i < 2; i++)
#pragma unroll
                    for (int j = 0; j < 2; j++) {
                        wmma::mma_sync(acc[i][j], ah[i], bh[j], acc[i][j]);
                        wmma::mma_sync(acc[i][j], ah[i], bl[j], acc[i][j]);
                        wmma::mma_sync(acc[i][j], al[i], bh[j], acc[i][j]);
                    }
            }
            __syncthreads();                   // reads done before next re-stage
        }
    };

    // in-place fp32 -> bf16 hi/lo convert of a [128][128] result at `base`
    auto convert = [&](int base) {
        float* t32 = (float*)(sm + base);
        const int r = tid >> 2, c0 = (tid & 3) * 32;
        float v[32];
#pragma unroll
        for (int jj = 0; jj < 8; jj++) {
            float4 f = *(const float4*)(t32 + r * SFP + c0 + jj * 4);
            v[jj * 4 + 0] = f.x; v[jj * 4 + 1] = f.y;
            v[jj * 4 + 2] = f.z; v[jj * 4 + 3] = f.w;
        }
        __syncthreads();                       // all fp32 read before overwrite
#pragma unroll
        for (int jj = 0; jj < 8; jj++) {
            unsigned h0, l0, h1, l1;
            split2(v[jj * 4 + 0], v[jj * 4 + 1], h0, l0);
            split2(v[jj * 4 + 2], v[jj * 4 + 3], h1, l1);
            *(uint2*)(sm + base + (r * SB + c0 + jj * 4) * 2) = make_uint2(h0, h1);
            *(uint2*)(sm + base + 34816 + (r * SB + c0 + jj * 4) * 2) = make_uint2(l0, l1);
        }
    };

    // ---- phase 0: load x (2 batches, 128 rows) -> bf16 hi/lo ----
    {
        const float4* gx = (const float4*)(x + xbase);
#pragma unroll
        for (int i = 0; i < 8; i++) {
            int idx = tid + i * NT;                  // 4096 float4
            int row = idx >> 5, c = (idx & 31) * 4;
            float4 f = gx[idx];
            unsigned h0, l0, h1, l1;
            split2(f.x, f.y, h0, l0);
            split2(f.z, f.w, h1, l1);
            *(uint2*)(sm + XHI + (row * SB + c) * 2) = make_uint2(h0, h1);
            *(uint2*)(sm + XLO + (row * SB + c) * 2) = make_uint2(l0, l1);
        }
    }
    __syncthreads();

    // ---- phase 1: T = X@G  ([128,128,128]) ----
    {
        FC acc[2][2];
#pragma unroll
        for (int i = 0; i < 2; i++)
#pragma unroll
            for (int j = 0; j < 2; j++) wmma::fill_fragment(acc[i][j], 0.0f);
        proj(0, acc);
        float* t32 = (float*)(sm + THI);
#pragma unroll
        for (int i = 0; i < 2; i++)
#pragma unroll
            for (int j = 0; j < 2; j++)
                wmma::store_matrix_sync(t32 + (m0 + 16 * i) * SFP + (n0 + 16 * j),
                                        acc[i][j], SFP, wmma::mem_row_major);
        __syncthreads();
        convert(THI);
        __syncthreads();
    }

    // ---- phase 2: per-batch scores = T_g @ X_g^T ([64,64,128] x2) ----
    {
        const int w8  = wid & 7;                  // warp within batch group
        const int sg  = wid >> 3;                 // batch handled by this warp
        const int sm0 = 64 * sg + 16 * (w8 >> 1); // global m row
        const int snl = 32 * (w8 & 1);            // batch-local n col
        const __nv_bfloat16* thi = (const __nv_bfloat16*)(sm + THI);
        const __nv_bfloat16* tlo = (const __nv_bfloat16*)(sm + TLO);
        FC acc[2];
        wmma::fill_fragment(acc[0], 0.0f);
        wmma::fill_fragment(acc[1], 0.0f);
#pragma unroll
        for (int k = 0; k < 128; k += 16) {
            FA th, tl;
            FBc xh[2], xl[2];
            wmma::load_matrix_sync(th, thi + sm0 * SB + k, SB);
            wmma::load_matrix_sync(tl, tlo + sm0 * SB + k, SB);
#pragma unroll
            for (int j = 0; j < 2; j++) {
                int nrow = 64 * sg + snl + 16 * j;        // global X row
                wmma::load_matrix_sync(xh[j], xhi + nrow * SB + k, SB);
                wmma::load_matrix_sync(xl[j], xlo + nrow * SB + k, SB);
            }
#pragma unroll
            for (int j = 0; j < 2; j++) {
                wmma::mma_sync(acc[j], th, xh[j], acc[j]);
                wmma::mma_sync(acc[j], th, xl[j], acc[j]);
                wmma::mma_sync(acc[j], tl, xh[j], acc[j]);
            }
        }
        __syncthreads();                          // all warps done reading T
        float* scp = (float*)(sm + THI);          // scores fp32 [128][SSC], local cols
#pragma unroll
        for (int j = 0; j < 2; j++)
            wmma::store_matrix_sync(scp + sm0 * SSC + snl + 16 * j, acc[j], SSC,
                                    wmma::mem_row_major);
        __syncthreads();
    }

    // ---- phase 3: softmax rows (128) -> P hi/lo [128][SP] ----
    {
        const float* scp = (const float*)(sm + THI);
        const int r = tid >> 2, q0 = (tid & 3) * 16;
        float s[16];
#pragma unroll
        for (int j = 0; j < 16; j += 4) {
            float4 f = *(const float4*)(scp + r * SSC + q0 + j);
            s[j] = f.x; s[j + 1] = f.y; s[j + 2] = f.z; s[j + 3] = f.w;
        }
        float mx = s[0];
#pragma unroll
        for (int j = 1; j < 16; j++) mx = fmaxf(mx, s[j]);
        mx = fmaxf(mx, __shfl_xor_sync(0xffffffffu, mx, 1));
        mx = fmaxf(mx, __shfl_xor_sync(0xffffffffu, mx, 2));
        float sum = 0.f;
#pragma unroll
        for (int j = 0; j < 16; j++) { s[j] = __expf(s[j] - mx); sum += s[j]; }
        sum += __shfl_xor_sync(0xffffffffu, sum, 1);
        sum += __shfl_xor_sync(0xffffffffu, sum, 2);
        const float inv = 1.0f / sum;
        __syncthreads();                          // all scores read before P write
#pragma unroll
        for (int j = 0; j < 16; j += 2) {
            unsigned h, l;
            split2(s[j] * inv, s[j + 1] * inv, h, l);
            *(unsigned*)(sm + PHI + (r * SP + q0 + j) * 2) = h;
            *(unsigned*)(sm + PLO + (r * SP + q0 + j) * 2) = l;
        }
    }
    __syncthreads();

    // ---- phase 4: V = X@Wv ([128,128,128]) ----
    {
        FC acc[2][2];
#pragma unroll
        for (int i = 0; i < 2; i++)
#pragma unroll
            for (int j = 0; j < 2; j++) wmma::fill_fragment(acc[i][j], 0.0f);
        proj(1, acc);
        float* v32 = (float*)(sm + VHI);
#pragma unroll
        for (int i = 0; i < 2; i++)
#pragma unroll
            for (int j = 0; j < 2; j++)
                wmma::store_matrix_sync(v32 + (m0 + 16 * i) * SFP + (n0 + 16 * j),
                                        acc[i][j], SFP, wmma::mem_row_major);
        __syncthreads();
        convert(VHI);
        __syncthreads();
    }

    // ---- phase 5: acc = P_g@V_g (block-diag), acc += X@Wr, relu, store ----
    {
        const __nv_bfloat16* phi = (const __nv_bfloat16*)(sm + PHI);
        const __nv_bfloat16* plo = (const __nv_bfloat16*)(sm + PLO);
        const __nv_bfloat16* vhi = (const __nv_bfloat16*)(sm + VHI);
        const __nv_bfloat16* vlo = (const __nv_bfloat16*)(sm + VLO);
        FC acc[2][2];
#pragma unroll
        for (int i = 0; i < 2; i++)
#pragma unroll
            for (int j = 0; j < 2; j++) wmma::fill_fragment(acc[i][j], 0.0f);

        // P_g @ V_g : K=64 batch-local; A rows = m0.. (global), B rows = 64g+k
#pragma unroll
        for (int k = 0; k < 64; k += 16) {
            FA ph[2], pl[2];
            FBr vh[2], vl[2];
#pragma unroll
            for (int i = 0; i < 2; i++) {
                wmma::load_matrix_sync(ph[i], phi + (m0 + 16 * i) * SP + k, SP);
                wmma::load_matrix_sync(pl[i], plo + (m0 + 16 * i) * SP + k, SP);
            }
#pragma unroll
            for (int j = 0; j < 2; j++) {
                wmma::load_matrix_sync(vh[j], vhi + (64 * g + k) * SB + n0 + 16 * j, SB);
                wmma::load_matrix_sync(vl[j], vlo + (64 * g + k) * SB + n0 + 16 * j, SB);
            }
#pragma unroll
            for (int i = 0; i < 2; i++)
#pragma unroll
                for (int j = 0; j < 2; j++) {
                    wmma::mma_sync(acc[i][j], ph[i], vh[j], acc[i][j]);
                    wmma::mma_sync(acc[i][j], ph[i], vl[j], acc[i][j]);
                    wmma::mma_sync(acc[i][j], pl[i], vh[j], acc[i][j]);
                }
        }
        __syncthreads();                       // before proj reuses staging buffers

        // += X @ Wr (quarter-staged, shared across both batches)
        proj(2, acc);

        float* outp = out + xbase;             // 128 contiguous rows of 128
#pragma unroll
        for (int i = 0; i < 2; i++)
#pragma unroll
            for (int j = 0; j < 2; j++) {
#pragma unroll
                for (int e = 0; e < acc[i][j].num_elements; e++)
                    acc[i][j].x[e] = fmaxf(acc[i][j].x[e], 0.0f);
                wmma::store_matrix_sync(outp + (m0 + 16 * i) * 128 + (n0 + 16 * j),
                                        acc[i][j], 128, wmma::mem_row_major);
            }
    }
}

extern "C" void kernel_launch(void* const* d_in, const int* in_sizes, int n_in,
                              void* d_out, int out_size) {
    const float* x  = (const float*)d_in[0];
    const float* Wq = (const float*)d_in[1];
    const float* Wk = (const float*)d_in[2];
    const float* Wv = (const float*)d_in[3];
    const float* Wr = (const float*)d_in[4];
    float* out = (float*)d_out;

    prep_all<<<256, 256>>>(Wq, Wk, Wv, Wr);
    cudaFuncSetAttribute(autoint_hmma,
                         cudaFuncAttributeMaxDynamicSharedMemorySize, SMEM_BYTES);
    autoint_hmma<<<4096, NT, SMEM_BYTES>>>(x, out);
}

// round 17
// speedup vs baseline: 1.2168x; 1.2168x over previous
#include <cuda_runtime.h>
#include <cuda_bf16.h>
#include <mma.h>
#include <cstdint>

using namespace nvcuda;

#define DI __device__ __forceinline__

static constexpr int NT  = 256;
static constexpr int SB  = 136;   // bf16 tile stride (elems)
static constexpr int SP  = 72;    // P (alphas) bf16 stride
static constexpr int SFP = 132;   // fp32 in-place convert stride
static constexpr int SSC = 68;    // fp32 scores stride
static constexpr int SWE = 24;    // W eighth-buffer stride (16 k + 8 pad), 48B rows

// ---- smem byte offsets (total 112640 B -> 2 CTAs/SM) ----
static constexpr int XHI = 0;         // x hi [64][SB]        17408
static constexpr int XLO = 17408;     // x lo                 17408
static constexpr int THI = 34816;     // T hi; then scores fp32; then P hi
static constexpr int TLO = 52224;     // T lo (dead after scores)
static constexpr int PHI = 34816;     // P hi [64][SP]  9216
static constexpr int PLO = 44032;     // P lo           9216 (ends 53248)
static constexpr int VHI = 53248;     // V hi (overlays dead T-lo tail)
static constexpr int VLO = 70656;     // V lo (ends 88064)
// two eighth-PAIR staging buffers: hi [128][SWE] (6144) + lo (6144) = 12288 each
static constexpr int EB0 = 88064;
static constexpr int EB1 = 100352;
static constexpr int SMEM_BYTES = 112640;

// prepped: slot0 = G^T (G = Wq·Wk^T), slot1 = Wv^T, slot2 = Wr^T (bf16 hi/lo)
__device__ __align__(16) __nv_bfloat16 g_Whi[3][128 * 128];
__device__ __align__(16) __nv_bfloat16 g_Wlo[3][128 * 128];

DI unsigned pack2(__nv_bfloat16 a, __nv_bfloat16 b) {
    return (unsigned)__bfloat16_as_ushort(a) | ((unsigned)__bfloat16_as_ushort(b) << 16);
}
DI void split2(float v0, float v1, unsigned& h, unsigned& l) {
    __nv_bfloat16 h0 = __float2bfloat16_rn(v0), h1 = __float2bfloat16_rn(v1);
    __nv_bfloat16 l0 = __float2bfloat16_rn(v0 - __bfloat162float(h0));
    __nv_bfloat16 l1 = __float2bfloat16_rn(v1 - __bfloat162float(h1));
    h = pack2(h0, h1); l = pack2(l0, l1);
}
DI void cpa16(uint32_t dst, const void* src) {
    asm volatile("cp.async.cg.shared.global [%0], [%1], 16;" :: "r"(dst), "l"(src));
}
#define CPA_COMMIT() asm volatile("cp.async.commit_group;" ::: "memory")
#define CPA_WAIT(n)  asm volatile("cp.async.wait_group %0;" :: "n"(n) : "memory")

// ------------------------------------------------ merged prep kernel
__global__ void prep_all(const float* __restrict__ Wq, const float* __restrict__ Wk,
                         const float* __restrict__ Wv, const float* __restrict__ Wr) {
    const int blk = blockIdx.x;
    if (blk < 128) {
        int gid = blk * 256 + threadIdx.x;
        int o = gid >> 1, half = gid & 1;
        int j = o >> 7, d = o & 127;
        const float4* wq = (const float4*)(Wq + d * 128) + half * 16;
        const float4* wk = (const float4*)(Wk + j * 128) + half * 16;
        float s = 0.f;
#pragma unroll
        for (int e = 0; e < 16; e++) {
            float4 a = wq[e], c = wk[e];
            s = fmaf(a.x, c.x, fmaf(a.y, c.y, fmaf(a.z, c.z, fmaf(a.w, c.w, s))));
        }
        s += __shfl_xor_sync(0xffffffffu, s, 1);
        if (!half) {
            __nv_bfloat16 hi = __float2bfloat16_rn(s);
            g_Whi[0][j * 128 + d] = hi;
            g_Wlo[0][j * 128 + d] = __float2bfloat16_rn(s - __bfloat162float(hi));
        }
    } else {
        int i = (blk - 128) * 256 + threadIdx.x;
        int p = i >> 14, rem = i & 16383;
        int d = rem >> 7, e = rem & 127;
        float w = (p ? Wr : Wv)[rem];
        __nv_bfloat16 hi = __float2bfloat16_rn(w);
        g_Whi[p + 1][e * 128 + d] = hi;
        g_Wlo[p + 1][e * 128 + d] = __float2bfloat16_rn(w - __bfloat162float(hi));
    }
}

// ---------------------------------------------------------------- main kernel
using FA  = wmma::fragment<wmma::matrix_a, 16, 16, 16, __nv_bfloat16, wmma::row_major>;
using FBc = wmma::fragment<wmma::matrix_b, 16, 16, 16, __nv_bfloat16, wmma::col_major>;
using FBr = wmma::fragment<wmma::matrix_b, 16, 16, 16, __nv_bfloat16, wmma::row_major>;
using FC  = wmma::fragment<wmma::accumulator, 16, 16, 16, float>;

__global__ __launch_bounds__(NT, 2)
void autoint_hmma(const float* __restrict__ x, float* __restrict__ out) {
    extern __shared__ __align__(16) char sm[];
    const uint32_t smb = (uint32_t)__cvta_generic_to_shared(sm);
    const int b   = blockIdx.x;
    const int tid = threadIdx.x;
    const int wid = tid >> 5;

    // 2x2 warp tiles for [64 x 128] GEMMs
    const int m0 = 32 * (wid >> 2);
    const int n0 = 32 * (wid & 3);

    const __nv_bfloat16* xhi = (const __nv_bfloat16*)(sm + XHI);
    const __nv_bfloat16* xlo = (const __nv_bfloat16*)(sm + XLO);

    // issue async stage of k-eighth e (16 cols) of proj `slot` into buffer `buf`.
    // One commit group = hi eighth + lo eighth (12288 B).
    auto stageE = [&](int slot, int e, int buf) {
        const char* gh = (const char*)g_Whi[slot];
        const char* gl = (const char*)g_Wlo[slot];
        const uint32_t base = smb + (buf ? EB1 : EB0);
        int row = tid >> 1, half = tid & 1;           // 256 chunks of 16B per matrix
        int soff = (row * 128 + e * 16 + half * 8) * 2;
        int doff = row * (SWE * 2) + half * 16;
        cpa16(base + doff, gh + soff);
        cpa16(base + 6144 + doff, gl + soff);
        CPA_COMMIT();
    };

    // pipelined 3-term projection: acc += X @ W[slot], K in 8 eighths.
    // Precondition: stageE(slot, 0, 0) already issued; no other groups pending.
    auto proj = [&](int slot, FC (&acc)[2][2]) {
#pragma unroll 1
        for (int e = 0; e < 8; e++) {
            const int buf = e & 1;
            if (e < 7) stageE(slot, e + 1, buf ^ 1);  // overlap next transfer
            if (e < 7) { CPA_WAIT(1); } else { CPA_WAIT(0); }   // stage e landed
            __syncthreads();                          // visible to all warps
            const __nv_bfloat16* wh = (const __nv_bfloat16*)(sm + (buf ? EB1 : EB0));
            const __nv_bfloat16* wl = (const __nv_bfloat16*)(sm + (buf ? EB1 : EB0) + 6144);
            const int k = e * 16;
            FA ah[2], al[2];
            FBc bh[2], bl[2];
#pragma unroll
            for (int i = 0; i < 2; i++) {
                wmma::load_matrix_sync(ah[i], xhi + (m0 + 16 * i) * SB + k, SB);
                wmma::load_matrix_sync(al[i], xlo + (m0 + 16 * i) * SB + k, SB);
            }
#pragma unroll
            for (int j = 0; j < 2; j++) {
                wmma::load_matrix_sync(bh[j], wh + (n0 + 16 * j) * SWE, SWE);
                wmma::load_matrix_sync(bl[j], wl + (n0 + 16 * j) * SWE, SWE);
            }
#pragma unroll
            for (int i = 0; i < 2; i++)
#pragma unroll
                for (int j = 0; j < 2; j++) {
                    wmma::mma_sync(acc[i][j], ah[i], bh[j], acc[i][j]);
                    wmma::mma_sync(acc[i][j], ah[i], bl[j], acc[i][j]);
                    wmma::mma_sync(acc[i][j], al[i], bh[j], acc[i][j]);
                }
            __syncthreads();                          // reads done before buf reuse
        }
    };

    // in-place fp32 -> bf16 hi/lo convert of a [64][128] result at `base`
    auto convert = [&](int base) {
        float* t32 = (float*)(sm + base);
        const int r = tid >> 2, c0 = (tid & 3) * 32;
        float v[32];
#pragma unroll
        for (int jj = 0; jj < 8; jj++) {
            float4 f = *(const float4*)(t32 + r * SFP + c0 + jj * 4);
            v[jj * 4 + 0] = f.x; v[jj * 4 + 1] = f.y;
            v[jj * 4 + 2] = f.z; v[jj * 4 + 3] = f.w;
        }
        __syncthreads();                              // all fp32 read before overwrite
#pragma unroll
        for (int jj = 0; jj < 8; jj++) {
            unsigned h0, l0, h1, l1;
            split2(v[jj * 4 + 0], v[jj * 4 + 1], h0, l0);
            split2(v[jj * 4 + 2], v[jj * 4 + 3], h1, l1);
            *(uint2*)(sm + base + (r * SB + c0 + jj * 4) * 2) = make_uint2(h0, h1);
            *(uint2*)(sm + base + 17408 + (r * SB + c0 + jj * 4) * 2) = make_uint2(l0, l1);
        }
    };

    // ---- phase 0: prologue-stage G eighth-0, then load x[b] -> bf16 hi/lo ----
    stageE(0, 0, 0);
    {
        const float4* gx = (const float4*)(x + (size_t)b * 8192);
#pragma unroll
        for (int i = 0; i < 8; i++) {
            int idx = tid + i * NT;
            int row = idx >> 5, c = (idx & 31) * 4;
            float4 f = gx[idx];
            unsigned h0, l0, h1, l1;
            split2(f.x, f.y, h0, l0);
            split2(f.z, f.w, h1, l1);
            *(uint2*)(sm + XHI + (row * SB + c) * 2) = make_uint2(h0, h1);
            *(uint2*)(sm + XLO + (row * SB + c) * 2) = make_uint2(l0, l1);
        }
    }
    __syncthreads();

    // ---- phase 1: T = X@G ----
    {
        FC acc[2][2];
#pragma unroll
        for (int i = 0; i < 2; i++)
#pragma unroll
            for (int j = 0; j < 2; j++) wmma::fill_fragment(acc[i][j], 0.0f);
        proj(0, acc);
        float* t32 = (float*)(sm + THI);
#pragma unroll
        for (int i = 0; i < 2; i++)
#pragma unroll
            for (int j = 0; j < 2; j++)
                wmma::store_matrix_sync(t32 + (m0 + 16 * i) * SFP + (n0 + 16 * j),
                                        acc[i][j], SFP, wmma::mem_row_major);
        __syncthreads();
        convert(THI);
        __syncthreads();
    }

    // ---- phase 2: scores = T @ X^T (64x64, K=128, all smem) ----
    {
        const int sm0 = 16 * (wid & 3);
        const int sn0 = 32 * (wid >> 2);
        const __nv_bfloat16* thi = (const __nv_bfloat16*)(sm + THI);
        const __nv_bfloat16* tlo = (const __nv_bfloat16*)(sm + TLO);
        FC acc[2];
        wmma::fill_fragment(acc[0], 0.0f);
        wmma::fill_fragment(acc[1], 0.0f);
#pragma unroll
        for (int k = 0; k < 128; k += 16) {
            FA th, tl;
            FBc xh[2], xl[2];
            wmma::load_matrix_sync(th, thi + sm0 * SB + k, SB);
            wmma::load_matrix_sync(tl, tlo + sm0 * SB + k, SB);
#pragma unroll
            for (int j = 0; j < 2; j++) {
                wmma::load_matrix_sync(xh[j], xhi + (sn0 + 16 * j) * SB + k, SB);
                wmma::load_matrix_sync(xl[j], xlo + (sn0 + 16 * j) * SB + k, SB);
            }
#pragma unroll
            for (int j = 0; j < 2; j++) {
                wmma::mma_sync(acc[j], th, xh[j], acc[j]);
                wmma::mma_sync(acc[j], th, xl[j], acc[j]);
                wmma::mma_sync(acc[j], tl, xh[j], acc[j]);
            }
        }
        __syncthreads();                       // all warps done reading T
        float* scp = (float*)(sm + THI);       // scores fp32 over dead T-hi
#pragma unroll
        for (int j = 0; j < 2; j++)
            wmma::store_matrix_sync(scp + sm0 * SSC + sn0 + 16 * j, acc[j], SSC,
                                    wmma::mem_row_major);
        __syncthreads();
    }

    // ---- phase 3: softmax -> P hi/lo (prologue-stage Wv eighth-0 first) ----
    stageE(1, 0, 0);
    {
        const float* scp = (const float*)(sm + THI);
        const int r = tid >> 2, q0 = (tid & 3) * 16;
        float s[16];
#pragma unroll
        for (int j = 0; j < 16; j += 4) {
            float4 f = *(const float4*)(scp + r * SSC + q0 + j);
            s[j] = f.x; s[j + 1] = f.y; s[j + 2] = f.z; s[j + 3] = f.w;
        }
        float mx = s[0];
#pragma unroll
        for (int j = 1; j < 16; j++) mx = fmaxf(mx, s[j]);
        mx = fmaxf(mx, __shfl_xor_sync(0xffffffffu, mx, 1));
        mx = fmaxf(mx, __shfl_xor_sync(0xffffffffu, mx, 2));
        float sum = 0.f;
#pragma unroll
        for (int j = 0; j < 16; j++) { s[j] = __expf(s[j] - mx); sum += s[j]; }
        sum += __shfl_xor_sync(0xffffffffu, sum, 1);
        sum += __shfl_xor_sync(0xffffffffu, sum, 2);
        const float inv = 1.0f / sum;
        __syncthreads();                       // all scores read before overwrite
#pragma unroll
        for (int j = 0; j < 16; j += 2) {
            unsigned h, l;
            split2(s[j] * inv, s[j + 1] * inv, h, l);
            *(unsigned*)(sm + PHI + (r * SP + q0 + j) * 2) = h;
            *(unsigned*)(sm + PLO + (r * SP + q0 + j) * 2) = l;
        }
    }
    __syncthreads();

    // ---- phase 4: V = X@Wv (overlays dead T-lo region) ----
    {
        FC acc[2][2];
#pragma unroll
        for (int i = 0; i < 2; i++)
#pragma unroll
            for (int j = 0; j < 2; j++) wmma::fill_fragment(acc[i][j], 0.0f);
        proj(1, acc);
        float* v32 = (float*)(sm + VHI);
#pragma unroll
        for (int i = 0; i < 2; i++)
#pragma unroll
            for (int j = 0; j < 2; j++)
                wmma::store_matrix_sync(v32 + (m0 + 16 * i) * SFP + (n0 + 16 * j),
                                        acc[i][j], SFP, wmma::mem_row_major);
        __syncthreads();
        convert(VHI);
        __syncthreads();
    }

    // ---- phase 5: acc = P@V (Wr eighth-0 prefetched), acc += X@Wr, relu, store
    {
        stageE(2, 0, 0);                       // hidden behind P@V
        const __nv_bfloat16* phi = (const __nv_bfloat16*)(sm + PHI);
        const __nv_bfloat16* plo = (const __nv_bfloat16*)(sm + PLO);
        const __nv_bfloat16* vhi = (const __nv_bfloat16*)(sm + VHI);
        const __nv_bfloat16* vlo = (const __nv_bfloat16*)(sm + VLO);
        FC acc[2][2];
#pragma unroll
        for (int i = 0; i < 2; i++)
#pragma unroll
            for (int j = 0; j < 2; j++) wmma::fill_fragment(acc[i][j], 0.0f);

        // P @ V : K=64, B row-major (smem)
#pragma unroll
        for (int k = 0; k < 64; k += 16) {
            FA ph[2], pl[2];
            FBr vh[2], vl[2];
#pragma unroll
            for (int i = 0; i < 2; i++) {
                wmma::load_matrix_sync(ph[i], phi + (m0 + 16 * i) * SP + k, SP);
                wmma::load_matrix_sync(pl[i], plo + (m0 + 16 * i) * SP + k, SP);
            }
#pragma unroll
            for (int j = 0; j < 2; j++) {
                wmma::load_matrix_sync(vh[j], vhi + k * SB + n0 + 16 * j, SB);
                wmma::load_matrix_sync(vl[j], vlo + k * SB + n0 + 16 * j, SB);
            }
#pragma unroll
            for (int i = 0; i < 2; i++)
#pragma unroll
                for (int j = 0; j < 2; j++) {
                    wmma::mma_sync(acc[i][j], ph[i], vh[j], acc[i][j]);
                    wmma::mma_sync(acc[i][j], ph[i], vl[j], acc[i][j]);
                    wmma::mma_sync(acc[i][j], pl[i], vh[j], acc[i][j]);
                }
        }

        // += X @ Wr (pipelined eighths; eighth-0 already in flight)
        proj(2, acc);

        float* outp = out + (size_t)b * 8192;
#pragma unroll
        for (int i = 0; i < 2; i++)
#pragma unroll
            for (int j = 0; j < 2; j++) {
#pragma unroll
                for (int e = 0; e < acc[i][j].num_elements; e++)
                    acc[i][j].x[e] = fmaxf(acc[i][j].x[e], 0.0f);
                wmma::store_matrix_sync(outp + (m0 + 16 * i) * 128 + (n0 + 16 * j),
                                        acc[i][j], 128, wmma::mem_row_major);
            }
    }
}

extern "C" void kernel_launch(void* const* d_in, const int* in_sizes, int n_in,
                              void* d_out, int out_size) {
    const float* x  = (const float*)d_in[0];
    const float* Wq = (const float*)d_in[1];
    const float* Wk = (const float*)d_in[2];
    const float* Wv = (const float*)d_in[3];
    const float* Wr = (const float*)d_in[4];
    float* out = (float*)d_out;

    prep_all<<<256, 256>>>(Wq, Wk, Wv, Wr);
    cudaFuncSetAttribute(autoint_hmma,
                         cudaFuncAttributeMaxDynamicSharedMemorySize, SMEM_BYTES);
    autoint_hmma<<<8192, NT, SMEM_BYTES>>>(x, out);
}